// round 13
// baseline (speedup 1.0000x reference)
#include <cuda_runtime.h>
#include <cuda_fp16.h>
#include <cstdint>

#define NN    100000
#define NPAD  100096
#define EE    1600000
#define HID   128
#define INDIM 20
#define NREL  3
#define NTYPE 4
#define LN_EPS 1e-5f

// ---------------- device scratch (no allocs allowed) ----------------
static __device__ float  g_h[(size_t)NN * HID];              // [x|agg]@B + b (pre-LN)
static __device__ __half g_agg[(size_t)NPAD * NREL * HID];   // per-relation x sums (fp16); pad rows stay 0
static __device__ __half g_xh[(size_t)NPAD * HID];           // x (fp16); pad rows stay 0
static __device__ __half g_Bw[2 * 512 * 128];                // weights B[jt*128+n][k] fp16, per layer
static __device__ int    g_cnt[NN];
static __device__ int    g_roff[NN];
static __device__ int    g_cur[NN];
static __device__ int    g_csr[EE];                          // (src<<2)|etype, grouped by dst
static __device__ int    g_bsum[512];
static __device__ int    g_tlist[(size_t)NTYPE * NN];
static __device__ int    g_tcount[NTYPE];
static __device__ float  g_pool[HID];

__device__ __forceinline__ void ldsm4(uint32_t* r, uint32_t a) {
    asm volatile("ldmatrix.sync.aligned.m8n8.x4.shared.b16 {%0,%1,%2,%3}, [%4];"
                 : "=r"(r[0]), "=r"(r[1]), "=r"(r[2]), "=r"(r[3]) : "r"(a));
}
__device__ __forceinline__ void cpa16(uint32_t s, const void* g) {
    asm volatile("cp.async.cg.shared.global [%0], [%1], 16;" :: "r"(s), "l"(g));
}

// ---------------- weight prep + all zero-init (fused) ----------------
__global__ void k_prepB(const float* __restrict__ relW, const float* __restrict__ linW) {
    int i = blockIdx.x * blockDim.x + threadIdx.x;
    if (i < NN) { g_cnt[i] = 0; g_cur[i] = 0; }
    if (i < NTYPE) g_tcount[i] = 0;
    if (i < HID) g_pool[i] = 0.f;
    if (i < 512) g_bsum[i] = 0;
    if (i >= 2 * 512 * 128) return;
    int l = i >> 16;
    int rem = i & 65535;
    int n = rem >> 7, k = rem & 127;
    int jt = n >> 7, c = n & 127;
    float v = (jt < 3) ? relW[(((size_t)l * 3 + jt) * 128 + k) * 128 + c]
                       : linW[((size_t)l * 128 + k) * 128 + c];
    g_Bw[i] = __float2half_rn(v);
}

// ---------------- bucketing + degree count (fused) ----------------
__global__ void k_bucket_cnt(const int* __restrict__ ntype, const int* __restrict__ dst) {
    int i = blockIdx.x * blockDim.x + threadIdx.x;
    if (i < NN) {
        int t = ntype[i];
        int pos = atomicAdd(&g_tcount[t], 1);
        g_tlist[(size_t)t * NN + pos] = i;
    }
    if (i < EE) atomicAdd(&g_cnt[dst[i]], 1);
}

__global__ void k_scan1() {
    __shared__ int sh[256];
    int i = blockIdx.x * 256 + threadIdx.x;
    int v = (i < NN) ? g_cnt[i] : 0;
    sh[threadIdx.x] = v;
    __syncthreads();
    for (int o = 1; o < 256; o <<= 1) {
        int t = (threadIdx.x >= o) ? sh[threadIdx.x - o] : 0;
        __syncthreads();
        sh[threadIdx.x] += t;
        __syncthreads();
    }
    if (i < NN) g_roff[i] = sh[threadIdx.x] - v;
    if (threadIdx.x == 255) g_bsum[blockIdx.x] = sh[255];
}

__global__ void k_scan2() {
    __shared__ int sh[512];
    int t = threadIdx.x;
    int v = g_bsum[t];
    sh[t] = v;
    __syncthreads();
    for (int o = 1; o < 512; o <<= 1) {
        int u = (t >= o) ? sh[t - o] : 0;
        __syncthreads();
        sh[t] += u;
        __syncthreads();
    }
    g_bsum[t] = sh[t] - v;
}

__global__ void k_scan3() {
    int i = blockIdx.x * blockDim.x + threadIdx.x;
    if (i >= NN) return;
    g_roff[i] += g_bsum[i >> 8];
}

__global__ void k_fill(const int* __restrict__ src, const int* __restrict__ dst,
                       const int* __restrict__ etyp) {
    int e = blockIdx.x * blockDim.x + threadIdx.x;
    if (e >= EE) return;
    int d = dst[e];
    int pos = g_roff[d] + atomicAdd(&g_cur[d], 1);
    g_csr[pos] = (src[e] << 2) | etyp[e];
}

// ---------------- type-specific encoder: stage1 SIMT, stage2 fp16 MMA ----------------
#define EKS 136
#define ENC_SMEM (2560 * 4 + 2688 * 4 + 2 * 128 * EKS * 2)

__global__ void __launch_bounds__(256, 1)
k_encoder(const int* __restrict__ z, const float* __restrict__ sd,
          const float* __restrict__ dfp, const float* __restrict__ cond,
          const float* __restrict__ mult, const float* __restrict__ zemb,
          const float* __restrict__ W1, const float* __restrict__ b1,
          const float* __restrict__ W2, const float* __restrict__ b2) {
    int t = blockIdx.y;
    int cnt = g_tcount[t];
    int start = blockIdx.x * 128;
    if (start >= cnt) return;

    extern __shared__ char smc[];
    float*  W1s  = (float*)smc;
    float*  raws = W1s + 2560;
    __half* Ah   = (__half*)(raws + 2688);
    __half* Bs   = Ah + 128 * EKS;
    __shared__ int nl[128];

    int tid = threadIdx.x;
    if (tid < 128) {
        int idx = start + tid;
        nl[tid] = g_tlist[(size_t)t * NN + (idx < cnt ? idx : cnt - 1)];
    }
    for (int i = tid; i < 640; i += 256)
        *(float4*)&W1s[i * 4] = *(const float4*)&W1[(size_t)t * 2560 + i * 4];
    for (int i = tid; i < 4096; i += 256) {
        int k = i >> 5, c4 = (i & 31) * 4;
        float4 w = *(const float4*)&W2[(size_t)t * 16384 + k * 128 + c4];
        Bs[(c4 + 0) * EKS + k] = __float2half_rn(w.x);
        Bs[(c4 + 1) * EKS + k] = __float2half_rn(w.y);
        Bs[(c4 + 2) * EKS + k] = __float2half_rn(w.z);
        Bs[(c4 + 3) * EKS + k] = __float2half_rn(w.w);
    }
    __syncthreads();

    for (int i = tid; i < 128 * INDIM; i += 256) {
        int n = i / INDIM, k = i % INDIM;
        int node = nl[n];
        float v;
        if (k < 16)       v = zemb[(size_t)z[node] * 16 + k];
        else if (k == 16) v = sd[node];
        else if (k == 17) v = dfp[node];
        else if (k == 18) v = cond[node];
        else              v = mult[node];
        raws[n * 21 + k] = v;
    }
    __syncthreads();

    {
        int n = tid & 127;
        float r20[INDIM];
#pragma unroll
        for (int k = 0; k < INDIM; k++) r20[k] = raws[n * 21 + k];
        int chalf = tid >> 7;
        for (int p = 0; p < 64; p++) {
            int c = chalf + p * 2;
            float s = b1[t * HID + c];
#pragma unroll
            for (int k = 0; k < INDIM; k++) s += r20[k] * W1s[k * 128 + c];
            Ah[n * EKS + c] = __float2half_rn(fmaxf(s, 0.f));
        }
    }
    __syncthreads();

    int wid = tid >> 5, lane = tid & 31;
    int wm = wid >> 1, wn = wid & 1;
    int g = lane >> 2, tc = lane & 3;

    float c[2][8][4];
#pragma unroll
    for (int mt = 0; mt < 2; mt++)
#pragma unroll
        for (int nt = 0; nt < 8; nt++)
#pragma unroll
            for (int q = 0; q < 4; q++) c[mt][nt][q] = 0.f;

#pragma unroll
    for (int k0 = 0; k0 < 8; k0++) {
        int kb = k0 * 16 + tc * 2;
        uint32_t a[2][4];
#pragma unroll
        for (int mt = 0; mt < 2; mt++) {
            int r0 = wm * 32 + mt * 16 + g;
            a[mt][0] = *(const uint32_t*)&Ah[r0 * EKS + kb];
            a[mt][1] = *(const uint32_t*)&Ah[(r0 + 8) * EKS + kb];
            a[mt][2] = *(const uint32_t*)&Ah[r0 * EKS + kb + 8];
            a[mt][3] = *(const uint32_t*)&Ah[(r0 + 8) * EKS + kb + 8];
        }
        uint32_t b[8][2];
#pragma unroll
        for (int nt = 0; nt < 8; nt++) {
            int col = wn * 64 + nt * 8 + g;
            b[nt][0] = *(const uint32_t*)&Bs[col * EKS + kb];
            b[nt][1] = *(const uint32_t*)&Bs[col * EKS + kb + 8];
        }
#pragma unroll
        for (int mt = 0; mt < 2; mt++)
#pragma unroll
            for (int nt = 0; nt < 8; nt++) {
                float* cc = c[mt][nt];
                asm volatile(
                    "mma.sync.aligned.m16n8k16.row.col.f32.f16.f16.f32 "
                    "{%0,%1,%2,%3}, {%4,%5,%6,%7}, {%8,%9}, {%0,%1,%2,%3};"
                    : "+f"(cc[0]), "+f"(cc[1]), "+f"(cc[2]), "+f"(cc[3])
                    : "r"(a[mt][0]), "r"(a[mt][1]), "r"(a[mt][2]), "r"(a[mt][3]),
                      "r"(b[nt][0]), "r"(b[nt][1]));
            }
    }

#pragma unroll
    for (int mt = 0; mt < 2; mt++) {
        int lr0 = wm * 32 + mt * 16 + g;
        int lr1 = lr0 + 8;
#pragma unroll
        for (int nt = 0; nt < 8; nt++) {
            int colLoc = wn * 64 + nt * 8 + tc * 2;
            float* cc = c[mt][nt];
            float b0 = b2[t * HID + colLoc], b1v = b2[t * HID + colLoc + 1];
            if (start + lr0 < cnt)
                *(__half2*)&g_xh[(size_t)nl[lr0] * HID + colLoc] =
                    __floats2half2_rn(cc[0] + b0, cc[1] + b1v);
            if (start + lr1 < cnt)
                *(__half2*)&g_xh[(size_t)nl[lr1] * HID + colLoc] =
                    __floats2half2_rn(cc[2] + b0, cc[3] + b1v);
        }
    }
}

// ---------------- per-relation x aggregation: agg_r[dst] = (sum x[src]) / deg ----------------
__global__ void __launch_bounds__(256)
k_aggx() {
    int warp = threadIdx.x >> 5, lane = threadIdx.x & 31;
    int node = blockIdx.x * 8 + warp;
    if (node >= NN) return;
    int base = g_roff[node];
    int cnt  = g_cnt[node];
    int c = lane * 4;

    float acc[3][4];
#pragma unroll
    for (int r = 0; r < 3; r++)
#pragma unroll
        for (int q = 0; q < 4; q++) acc[r][q] = 0.f;

    int v[8];
#pragma unroll
    for (int q = 0; q < 8; q++)
        v[q] = (q < cnt) ? __ldg(&g_csr[base + q]) : -1;

    int nb = (cnt + 7) >> 3;
    for (int bi = 0; bi < nb; bi++) {
        int vn[8];
        int nb0 = (bi + 1) * 8;
#pragma unroll
        for (int q = 0; q < 8; q++)
            vn[q] = (nb0 + q < cnt) ? __ldg(&g_csr[base + nb0 + q]) : -1;

        uint2 u[8];
#pragma unroll
        for (int q = 0; q < 8; q++) {
            if (v[q] >= 0) {
                int s = v[q] >> 2;
                u[q] = *(const uint2*)&g_xh[(size_t)s * HID + c];
            } else {
                u[q] = make_uint2(0u, 0u);
            }
        }
#pragma unroll
        for (int q = 0; q < 8; q++) {
            if (v[q] >= 0) {
                float2 f0 = __half22float2(*(__half2*)&u[q].x);
                float2 f1 = __half22float2(*(__half2*)&u[q].y);
                int r = v[q] & 3;   // warp-uniform (broadcast csr word)
                if (r == 0) {
                    acc[0][0] += f0.x; acc[0][1] += f0.y; acc[0][2] += f1.x; acc[0][3] += f1.y;
                } else if (r == 1) {
                    acc[1][0] += f0.x; acc[1][1] += f0.y; acc[1][2] += f1.x; acc[1][3] += f1.y;
                } else {
                    acc[2][0] += f0.x; acc[2][1] += f0.y; acc[2][2] += f1.x; acc[2][3] += f1.y;
                }
            }
        }
#pragma unroll
        for (int q = 0; q < 8; q++) v[q] = vn[q];
    }

    float di = 1.0f / fmaxf((float)cnt, 1.0f);
#pragma unroll
    for (int r = 0; r < 3; r++) {
        __half2 h0 = __floats2half2_rn(acc[r][0] * di, acc[r][1] * di);
        __half2 h1 = __floats2half2_rn(acc[r][2] * di, acc[r][3] * di);
        *(float2*)&g_agg[(size_t)node * 384 + r * 128 + c] =
            make_float2(__uint_as_float(*(uint32_t*)&h0), __uint_as_float(*(uint32_t*)&h1));
    }
}

// ---------------- K=512 GEMM: h = [x | agg0 | agg1 | agg2] @ [lin; R0; R1; R2] + b ----------------
// 8 stages of [128 rows x 64 k], A+B double-buffered cp.async, accumulators persist.
#define KS2 72
#define STG (128 * KS2)                    // halfs per tile (9216)
#define MMA2_SMEM (4 * STG * 2)            // 73728 bytes -> 2 CTAs/SM

__global__ void __launch_bounds__(256, 2)
k_mma2(int l, const float* __restrict__ linb) {
    extern __shared__ __half sm2[];
    int tid = threadIdx.x;
    int wid = tid >> 5, lane = tid & 31;
    int rowBase = blockIdx.x * 128;
    uint32_t sbase = (uint32_t)__cvta_generic_to_shared(sm2);

    const __half* gBl = g_Bw + (size_t)l * 512 * 128;

    // stage s: kc = s>>1 (0=x/lin, 1..3=agg_r/R_r), koff = (s&1)*64
#define ISSUE_STAGE(s_)                                                              \
    do {                                                                             \
        int kc_ = (s_) >> 1, koff_ = ((s_) & 1) * 64;                                \
        uint32_t bufA_ = sbase + ((s_) & 1) * (2 * STG * 2);                         \
        uint32_t bufB_ = bufA_ + STG * 2;                                            \
        for (int i_ = tid; i_ < 1024; i_ += 256) {                                   \
            int row_ = i_ >> 3, k8_ = (i_ & 7) * 8;                                  \
            const __half* srcA_ = (kc_ == 0)                                         \
                ? g_xh + (size_t)(rowBase + row_) * 128 + koff_ + k8_                \
                : g_agg + (size_t)(rowBase + row_) * 384 + (kc_ - 1) * 128 + koff_ + k8_; \
            cpa16(bufA_ + (row_ * KS2 + k8_) * 2, srcA_);                            \
        }                                                                            \
        int jt_ = (kc_ == 0) ? 3 : (kc_ - 1);                                        \
        const __half* gB_ = gBl + (size_t)jt_ * 128 * 128;                           \
        for (int i_ = tid; i_ < 1024; i_ += 256) {                                   \
            int n_ = i_ >> 3, k8_ = (i_ & 7) * 8;                                    \
            cpa16(bufB_ + (n_ * KS2 + k8_) * 2, gB_ + (size_t)n_ * 128 + koff_ + k8_); \
        }                                                                            \
        asm volatile("cp.async.commit_group;" ::: "memory");                         \
    } while (0)

    ISSUE_STAGE(0);

    int wm = wid >> 1, wn = wid & 1;
    int sel = lane >> 3, lr = lane & 7;
    int g = lane >> 2, tc = lane & 3;

    int arow = wm * 32 + lr + ((sel & 1) << 3);
    int acol = (sel & 2) << 2;
    uint32_t aOff = (arow * KS2 + acol) * 2;
    int brow = wn * 64 + lr + ((sel & 2) << 2);
    int bcol = (sel & 1) << 3;
    uint32_t bOff = (brow * KS2 + bcol) * 2;

    float c[2][8][4];
#pragma unroll
    for (int mt = 0; mt < 2; mt++)
#pragma unroll
        for (int nt = 0; nt < 8; nt++)
#pragma unroll
            for (int q = 0; q < 4; q++) c[mt][nt][q] = 0.f;

    for (int s = 0; s < 8; s++) {
        if (s < 7) {
            ISSUE_STAGE(s + 1);
            asm volatile("cp.async.wait_group 1;" ::: "memory");
        } else {
            asm volatile("cp.async.wait_group 0;" ::: "memory");
        }
        __syncthreads();
        uint32_t bufA = sbase + (s & 1) * (2 * STG * 2);
        uint32_t bufB = bufA + STG * 2;

#pragma unroll
        for (int k0 = 0; k0 < 4; k0++) {
            uint32_t a[2][4];
            ldsm4(a[0], bufA + aOff + k0 * 32);
            ldsm4(a[1], bufA + aOff + 16 * KS2 * 2 + k0 * 32);
            uint32_t b[4][4];
#pragma unroll
            for (int ntp = 0; ntp < 4; ntp++)
                ldsm4(b[ntp], bufB + bOff + ntp * 16 * KS2 * 2 + k0 * 32);
#pragma unroll
            for (int mt = 0; mt < 2; mt++)
#pragma unroll
                for (int ntp = 0; ntp < 4; ntp++) {
                    float* c0 = c[mt][ntp * 2];
                    float* c1 = c[mt][ntp * 2 + 1];
                    asm volatile(
                        "mma.sync.aligned.m16n8k16.row.col.f32.f16.f16.f32 "
                        "{%0,%1,%2,%3}, {%4,%5,%6,%7}, {%8,%9}, {%0,%1,%2,%3};"
                        : "+f"(c0[0]), "+f"(c0[1]), "+f"(c0[2]), "+f"(c0[3])
                        : "r"(a[mt][0]), "r"(a[mt][1]), "r"(a[mt][2]), "r"(a[mt][3]),
                          "r"(b[ntp][0]), "r"(b[ntp][1]));
                    asm volatile(
                        "mma.sync.aligned.m16n8k16.row.col.f32.f16.f16.f32 "
                        "{%0,%1,%2,%3}, {%4,%5,%6,%7}, {%8,%9}, {%0,%1,%2,%3};"
                        : "+f"(c1[0]), "+f"(c1[1]), "+f"(c1[2]), "+f"(c1[3])
                        : "r"(a[mt][0]), "r"(a[mt][1]), "r"(a[mt][2]), "r"(a[mt][3]),
                          "r"(b[ntp][2]), "r"(b[ntp][3]));
                }
        }
        __syncthreads();
    }

    // epilogue: h = C + linb
#pragma unroll
    for (int mt = 0; mt < 2; mt++) {
        int row0 = rowBase + wm * 32 + mt * 16 + g;
        int row1 = row0 + 8;
#pragma unroll
        for (int nt = 0; nt < 8; nt++) {
            int colLoc = wn * 64 + nt * 8 + tc * 2;
            float* cc = c[mt][nt];
            float b0 = linb[colLoc], b1 = linb[colLoc + 1];
            if (row0 < NN)
                *(float2*)&g_h[(size_t)row0 * 128 + colLoc] = make_float2(cc[0] + b0, cc[1] + b1);
            if (row1 < NN)
                *(float2*)&g_h[(size_t)row1 * 128 + colLoc] = make_float2(cc[2] + b0, cc[3] + b1);
        }
    }
#undef ISSUE_STAGE
}

// ---------------- LayerNorm: x = LN(h)*g + b ----------------
__global__ void __launch_bounds__(256)
k_ln(const float* __restrict__ gg, const float* __restrict__ gb, int mode) {
    __shared__ float shp[8][128];
    int warp = threadIdx.x >> 5, lane = threadIdx.x & 31;
    int node = blockIdx.x * 8 + warp;
    bool live = node < NN;
    float4 o = make_float4(0.f, 0.f, 0.f, 0.f);
    int c = lane * 4;

    if (live) {
        float4 hv = *(const float4*)&g_h[(size_t)node * HID + c];
        float s = hv.x + hv.y + hv.z + hv.w;
#pragma unroll
        for (int of = 16; of; of >>= 1) s += __shfl_xor_sync(0xFFFFFFFFu, s, of);
        float mu = s * (1.0f / HID);
        float dx = hv.x - mu, dy = hv.y - mu, dz = hv.z - mu, dw = hv.w - mu;
        float s2 = dx * dx + dy * dy + dz * dz + dw * dw;
#pragma unroll
        for (int of = 16; of; of >>= 1) s2 += __shfl_xor_sync(0xFFFFFFFFu, s2, of);
        float rs = rsqrtf(s2 * (1.0f / HID) + LN_EPS);

        float4 g4 = *(const float4*)&gg[c];
        float4 b4 = *(const float4*)&gb[c];
        o = make_float4(dx * rs * g4.x + b4.x, dy * rs * g4.y + b4.y,
                        dz * rs * g4.z + b4.z, dw * rs * g4.w + b4.w);
    }

    if (mode == 0) {
        if (live) {
            __half2 h0 = __floats2half2_rn(o.x, o.y);
            __half2 h1 = __floats2half2_rn(o.z, o.w);
            *(float2*)&g_xh[(size_t)node * HID + c] =
                make_float2(__uint_as_float(*(uint32_t*)&h0), __uint_as_float(*(uint32_t*)&h1));
        }
    } else {
        shp[warp][c]     = o.x;
        shp[warp][c + 1] = o.y;
        shp[warp][c + 2] = o.z;
        shp[warp][c + 3] = o.w;
        __syncthreads();
        if (threadIdx.x < 128) {
            float s = 0.f;
#pragma unroll
            for (int w = 0; w < 8; w++) s += shp[w][threadIdx.x];
            atomicAdd(&g_pool[threadIdx.x], s);
        }
    }
}

// ---------------- regressor ----------------
__global__ void k_final(const float* __restrict__ regW, const float* __restrict__ regb,
                        float* __restrict__ out) {
    int c = threadIdx.x;
    __shared__ float red[HID];
    red[c] = g_pool[c] * (1.0f / NN) * regW[c];
    __syncthreads();
    for (int s = 64; s; s >>= 1) {
        if (c < s) red[c] += red[c + s];
        __syncthreads();
    }
    if (c == 0) out[0] = red[0] + regb[0];
}

// ---------------- launch ----------------
extern "C" void kernel_launch(void* const* d_in, const int* in_sizes, int n_in,
                              void* d_out, int out_size) {
    const int*   z     = (const int*)d_in[0];
    const float* sd    = (const float*)d_in[1];
    const float* dfp   = (const float*)d_in[2];
    const float* cond  = (const float*)d_in[3];
    const float* mult  = (const float*)d_in[4];
    const int*   ntype = (const int*)d_in[5];
    const int*   eidx  = (const int*)d_in[6];
    const int*   etyp  = (const int*)d_in[7];
    const float* zemb  = (const float*)d_in[8];
    const float* eW1   = (const float*)d_in[9];
    const float* eb1   = (const float*)d_in[10];
    const float* eW2   = (const float*)d_in[11];
    const float* eb2   = (const float*)d_in[12];
    const float* linW  = (const float*)d_in[13];
    const float* linb  = (const float*)d_in[14];
    const float* relW  = (const float*)d_in[15];
    const float* lng   = (const float*)d_in[16];
    const float* lnb   = (const float*)d_in[17];
    const float* regW  = (const float*)d_in[18];
    const float* regb  = (const float*)d_in[19];
    float* out = (float*)d_out;

    cudaFuncSetAttribute(k_encoder, cudaFuncAttributeMaxDynamicSharedMemorySize, ENC_SMEM);
    cudaFuncSetAttribute(k_mma2, cudaFuncAttributeMaxDynamicSharedMemorySize, MMA2_SMEM);

    const int rowBlocks = NPAD / 128;   // 782

    k_prepB<<<512, 256>>>(relW, linW);                         // 1 (weights + all zero-init)
    k_bucket_cnt<<<(EE + 255) / 256, 256>>>(ntype, eidx + EE); // 2
    k_scan1<<<(NN + 255) / 256, 256>>>();                      // 3
    k_encoder<<<dim3(rowBlocks, NTYPE), 256, ENC_SMEM>>>(      // 4  <-- ncu (encoder profile)
        z, sd, dfp, cond, mult, zemb, eW1, eb1, eW2, eb2);
    k_scan2<<<1, 512>>>();                                     // 5
    k_scan3<<<(NN + 255) / 256, 256>>>();                      // 6
    k_fill<<<(EE + 255) / 256, 256>>>(eidx, eidx + EE, etyp);  // 7
    for (int l = 0; l < 2; l++) {
        k_aggx<<<(NN + 7) / 8, 256>>>();                       // 8 / 11
        k_mma2<<<rowBlocks, 256, MMA2_SMEM>>>(l, linb + l * HID); // 9 / 12
        k_ln<<<(NN + 7) / 8, 256>>>(lng + l * HID, lnb + l * HID, l); // 10 / 13
    }
    k_final<<<1, 128>>>(regW, regb, out);                      // 14
}

// round 14
// speedup vs baseline: 1.2631x; 1.2631x over previous
#include <cuda_runtime.h>
#include <cuda_fp16.h>
#include <cstdint>

#define NN    100000
#define NPAD  100096
#define EE    1600000
#define HID   128
#define INDIM 20
#define NREL  3
#define NTYPE 4
#define LN_EPS 1e-5f

// ---------------- device scratch (no allocs allowed) ----------------
static __device__ float  g_h[(size_t)NN * HID];            // x@lin + b (pre-agg)
static __device__ __half g_yh[(size_t)NN * NREL * HID];    // per-relation feats fp16 (76.8MB)
static __device__ __half g_xh[(size_t)NPAD * HID];         // x (fp16); pad rows stay 0
static __device__ __half g_Bw[2 * 512 * 128];              // weights B[n][k] fp16, per layer
static __device__ int    g_cnt[NN];
static __device__ int    g_roff[NN];
static __device__ int    g_cur[NN];
static __device__ int    g_csr[EE];                        // (src<<2)|etype, grouped by dst
static __device__ int    g_bsum[512];
static __device__ int    g_tlist[(size_t)NTYPE * NN];
static __device__ int    g_tcount[NTYPE];
static __device__ float  g_pool[HID];

__device__ __forceinline__ void ldsm4(uint32_t* r, uint32_t a) {
    asm volatile("ldmatrix.sync.aligned.m8n8.x4.shared.b16 {%0,%1,%2,%3}, [%4];"
                 : "=r"(r[0]), "=r"(r[1]), "=r"(r[2]), "=r"(r[3]) : "r"(a));
}
__device__ __forceinline__ void ldsm4t(uint32_t* r, uint32_t a) {
    asm volatile("ldmatrix.sync.aligned.m8n8.x4.trans.shared.b16 {%0,%1,%2,%3}, [%4];"
                 : "=r"(r[0]), "=r"(r[1]), "=r"(r[2]), "=r"(r[3]) : "r"(a));
}
__device__ __forceinline__ void cpa16(uint32_t s, const void* g) {
    asm volatile("cp.async.cg.shared.global [%0], [%1], 16;" :: "r"(s), "l"(g));
}

// ---------------- weight prep + all zero-init (fused) ----------------
__global__ void k_prepB(const float* __restrict__ relW, const float* __restrict__ linW) {
    int i = blockIdx.x * blockDim.x + threadIdx.x;
    if (i < NN) { g_cnt[i] = 0; g_cur[i] = 0; }
    if (i < NTYPE) g_tcount[i] = 0;
    if (i < HID) g_pool[i] = 0.f;
    if (i < 512) g_bsum[i] = 0;
    if (i >= 2 * 512 * 128) return;
    int l = i >> 16;
    int rem = i & 65535;
    int n = rem >> 7, k = rem & 127;
    int jt = n >> 7, c = n & 127;
    float v = (jt < 3) ? relW[(((size_t)l * 3 + jt) * 128 + k) * 128 + c]
                       : linW[((size_t)l * 128 + k) * 128 + c];
    g_Bw[i] = __float2half_rn(v);
}

// ---------------- bucketing + degree count (fused) ----------------
__global__ void k_bucket_cnt(const int* __restrict__ ntype, const int* __restrict__ dst) {
    int i = blockIdx.x * blockDim.x + threadIdx.x;
    if (i < NN) {
        int t = ntype[i];
        int pos = atomicAdd(&g_tcount[t], 1);
        g_tlist[(size_t)t * NN + pos] = i;
    }
    if (i < EE) atomicAdd(&g_cnt[dst[i]], 1);
}

__global__ void k_scan1() {
    __shared__ int sh[256];
    int i = blockIdx.x * 256 + threadIdx.x;
    int v = (i < NN) ? g_cnt[i] : 0;
    sh[threadIdx.x] = v;
    __syncthreads();
    for (int o = 1; o < 256; o <<= 1) {
        int t = (threadIdx.x >= o) ? sh[threadIdx.x - o] : 0;
        __syncthreads();
        sh[threadIdx.x] += t;
        __syncthreads();
    }
    if (i < NN) g_roff[i] = sh[threadIdx.x] - v;
    if (threadIdx.x == 255) g_bsum[blockIdx.x] = sh[255];
}

__global__ void k_scan2() {
    __shared__ int sh[512];
    int t = threadIdx.x;
    int v = g_bsum[t];
    sh[t] = v;
    __syncthreads();
    for (int o = 1; o < 512; o <<= 1) {
        int u = (t >= o) ? sh[t - o] : 0;
        __syncthreads();
        sh[t] += u;
        __syncthreads();
    }
    g_bsum[t] = sh[t] - v;
}

__global__ void k_scan3() {
    int i = blockIdx.x * blockDim.x + threadIdx.x;
    if (i >= NN) return;
    g_roff[i] += g_bsum[i >> 8];
}

__global__ void k_fill(const int* __restrict__ src, const int* __restrict__ dst,
                       const int* __restrict__ etyp) {
    int e = blockIdx.x * blockDim.x + threadIdx.x;
    if (e >= EE) return;
    int d = dst[e];
    int pos = g_roff[d] + atomicAdd(&g_cur[d], 1);
    g_csr[pos] = (src[e] << 2) | etyp[e];
}

// ---------------- type-specific encoder: stage1 SIMT, stage2 fp16 MMA (trans-ldsm B) ----------------
#define EKS 136
// W1s(2560f) + raws(2688f) + b1s(128f) + Ah(128*EKS h) + W2s(128*EKS h, ROW-major [k][c])
#define ENC_SMEM ((2560 + 2688 + 128) * 4 + 2 * 128 * EKS * 2)

__global__ void __launch_bounds__(256, 2)
k_encoder(const int* __restrict__ z, const float* __restrict__ sd,
          const float* __restrict__ dfp, const float* __restrict__ cond,
          const float* __restrict__ mult, const float* __restrict__ zemb,
          const float* __restrict__ W1, const float* __restrict__ b1,
          const float* __restrict__ W2, const float* __restrict__ b2) {
    int t = blockIdx.y;
    int cnt = g_tcount[t];
    int start = blockIdx.x * 128;
    if (start >= cnt) return;

    extern __shared__ char smc[];
    float*  W1s  = (float*)smc;           // [20][128]
    float*  raws = W1s + 2560;            // [128][21]
    float*  b1s  = raws + 2688;           // [128]
    __half* Ah   = (__half*)(b1s + 128);  // [128 n][EKS]  (h1, row-major n x k)
    __half* W2s  = Ah + 128 * EKS;        // [128 k][EKS]  (W2 row-major k x c)
    __shared__ int nl[128];

    int tid = threadIdx.x;
    if (tid < 128) {
        int idx = start + tid;
        nl[tid] = g_tlist[(size_t)t * NN + (idx < cnt ? idx : cnt - 1)];
        b1s[tid] = b1[t * HID + tid];
    }
    for (int i = tid; i < 640; i += 256)
        *(float4*)&W1s[i * 4] = *(const float4*)&W1[(size_t)t * 2560 + i * 4];
    // W2 [k][c] row-major into smem (coalesced, conflict-free)
    for (int i = tid; i < 4096; i += 256) {
        int k = i >> 5, c4 = (i & 31) * 4;
        float4 w = *(const float4*)&W2[(size_t)t * 16384 + k * 128 + c4];
        __half2 h0 = __floats2half2_rn(w.x, w.y);
        __half2 h1 = __floats2half2_rn(w.z, w.w);
        *(float2*)&W2s[k * EKS + c4] =
            make_float2(__uint_as_float(*(uint32_t*)&h0), __uint_as_float(*(uint32_t*)&h1));
    }
    __syncthreads();

    for (int i = tid; i < 128 * INDIM; i += 256) {
        int n = i / INDIM, k = i % INDIM;
        int node = nl[n];
        float v;
        if (k < 16)       v = zemb[(size_t)z[node] * 16 + k];
        else if (k == 16) v = sd[node];
        else if (k == 17) v = dfp[node];
        else if (k == 18) v = cond[node];
        else              v = mult[node];
        raws[n * 21 + k] = v;
    }
    __syncthreads();

    // stage 1: Ah[n][c] = relu(raw[n].W1[:,c] + b1[c]) as fp16
    {
        int n = tid & 127;
        float r20[INDIM];
#pragma unroll
        for (int k = 0; k < INDIM; k++) r20[k] = raws[n * 21 + k];
        int chalf = tid >> 7;
        for (int p = 0; p < 64; p++) {
            int c = chalf + p * 2;
            float s = b1s[c];
#pragma unroll
            for (int k = 0; k < INDIM; k++) s += r20[k] * W1s[k * 128 + c];
            Ah[n * EKS + c] = __float2half_rn(fmaxf(s, 0.f));
        }
    }
    __syncthreads();

    // stage 2: out = Ah @ W2 (+b2); A via ldsm, B via ldsm.trans from row-major W2s
    int wid = tid >> 5, lane = tid & 31;
    int wm = wid >> 1, wn = wid & 1;
    int g = lane >> 2, tc = lane & 3;
    int sel = lane >> 3, lr = lane & 7;

    uint32_t ahBase = (uint32_t)__cvta_generic_to_shared(Ah);
    uint32_t w2Base = (uint32_t)__cvta_generic_to_shared(W2s);
    uint32_t aAddr = ahBase + ((wm * 32 + lr + ((sel & 1) << 3)) * EKS + ((sel & 2) << 2)) * 2;
    // B trans: rows = k, cols = c. sel bit0 -> k+8, sel bit1 -> c+8 (reg order matches k_mma)
    uint32_t bAddr = w2Base + (((lr + ((sel & 1) << 3)) * EKS) + wn * 64 + ((sel & 2) << 2)) * 2;

    float c[2][8][4];
#pragma unroll
    for (int mt = 0; mt < 2; mt++)
#pragma unroll
        for (int nt = 0; nt < 8; nt++)
#pragma unroll
            for (int q = 0; q < 4; q++) c[mt][nt][q] = 0.f;

#pragma unroll
    for (int k0 = 0; k0 < 8; k0++) {
        uint32_t a[2][4];
        ldsm4(a[0], aAddr + k0 * 32);
        ldsm4(a[1], aAddr + 16 * EKS * 2 + k0 * 32);
        uint32_t b[4][4];
#pragma unroll
        for (int pr = 0; pr < 4; pr++)
            ldsm4t(b[pr], bAddr + k0 * 16 * EKS * 2 + pr * 32);
#pragma unroll
        for (int mt = 0; mt < 2; mt++)
#pragma unroll
            for (int pr = 0; pr < 4; pr++) {
                float* c0 = c[mt][pr * 2];
                float* c1 = c[mt][pr * 2 + 1];
                asm volatile(
                    "mma.sync.aligned.m16n8k16.row.col.f32.f16.f16.f32 "
                    "{%0,%1,%2,%3}, {%4,%5,%6,%7}, {%8,%9}, {%0,%1,%2,%3};"
                    : "+f"(c0[0]), "+f"(c0[1]), "+f"(c0[2]), "+f"(c0[3])
                    : "r"(a[mt][0]), "r"(a[mt][1]), "r"(a[mt][2]), "r"(a[mt][3]),
                      "r"(b[pr][0]), "r"(b[pr][1]));
                asm volatile(
                    "mma.sync.aligned.m16n8k16.row.col.f32.f16.f16.f32 "
                    "{%0,%1,%2,%3}, {%4,%5,%6,%7}, {%8,%9}, {%0,%1,%2,%3};"
                    : "+f"(c1[0]), "+f"(c1[1]), "+f"(c1[2]), "+f"(c1[3])
                    : "r"(a[mt][0]), "r"(a[mt][1]), "r"(a[mt][2]), "r"(a[mt][3]),
                      "r"(b[pr][2]), "r"(b[pr][3]));
            }
    }

#pragma unroll
    for (int mt = 0; mt < 2; mt++) {
        int lr0 = wm * 32 + mt * 16 + g;
        int lr1 = lr0 + 8;
#pragma unroll
        for (int nt = 0; nt < 8; nt++) {
            int colLoc = wn * 64 + nt * 8 + tc * 2;
            float* cc = c[mt][nt];
            float b0 = b2[t * HID + colLoc], b1v = b2[t * HID + colLoc + 1];
            if (start + lr0 < cnt)
                *(__half2*)&g_xh[(size_t)nl[lr0] * HID + colLoc] =
                    __floats2half2_rn(cc[0] + b0, cc[1] + b1v);
            if (start + lr1 < cnt)
                *(__half2*)&g_xh[(size_t)nl[lr1] * HID + colLoc] =
                    __floats2half2_rn(cc[2] + b0, cc[3] + b1v);
        }
    }
}

// ---------------- fp16 mma GEMM: LDSM fragments + cp.async double-buffered B ----------------
#define KS 136
#define AB (128 * KS)
#define MMA_SMEM ((AB + 2 * AB) * 2)

__global__ void __launch_bounds__(256, 2)
k_mma(int l, const float* __restrict__ linb) {
    extern __shared__ __half smh[];
    int tid = threadIdx.x;
    int wid = tid >> 5, lane = tid & 31;
    int rowBase = blockIdx.x * 128;
    uint32_t sbase = (uint32_t)__cvta_generic_to_shared(smh);

    for (int i = tid; i < 2048; i += 256) {
        int row = i >> 4, kc = (i & 15) * 8;
        cpa16(sbase + (row * KS + kc) * 2, &g_xh[(size_t)(rowBase + row) * 128 + kc]);
    }
    const __half* gB = g_Bw + (size_t)l * 512 * 128;
    for (int i = tid; i < 2048; i += 256) {
        int row = i >> 4, kc = (i & 15) * 8;
        cpa16(sbase + (AB + row * KS + kc) * 2, gB + (size_t)row * 128 + kc);
    }
    asm volatile("cp.async.commit_group;" ::: "memory");

    int wm = wid >> 1, wn = wid & 1;
    int sel = lane >> 3, lr = lane & 7;
    int g = lane >> 2, tc = lane & 3;

    int arow = wm * 32 + lr + ((sel & 1) << 3);
    int acol = (sel & 2) << 2;
    uint32_t aAddr = sbase + (arow * KS + acol) * 2;
    int brow = wn * 64 + lr + ((sel & 2) << 2);
    int bcol = (sel & 1) << 3;
    uint32_t bOff = (brow * KS + bcol) * 2;

    for (int jt = 0; jt < 4; jt++) {
        asm volatile("cp.async.wait_group 0;" ::: "memory");
        __syncthreads();
        if (jt < 3) {
            const __half* gBn = gB + (size_t)(jt + 1) * 128 * 128;
            int bufn = (jt + 1) & 1;
            for (int i = tid; i < 2048; i += 256) {
                int row = i >> 4, kc = (i & 15) * 8;
                cpa16(sbase + (AB + bufn * AB + row * KS + kc) * 2,
                      gBn + (size_t)row * 128 + kc);
            }
            asm volatile("cp.async.commit_group;" ::: "memory");
        }
        uint32_t bAddr = sbase + (AB + (jt & 1) * AB) * 2 + bOff;

        float c[2][8][4];
#pragma unroll
        for (int mt = 0; mt < 2; mt++)
#pragma unroll
            for (int nt = 0; nt < 8; nt++)
#pragma unroll
                for (int q = 0; q < 4; q++) c[mt][nt][q] = 0.f;

#pragma unroll
        for (int k0 = 0; k0 < 8; k0++) {
            uint32_t a[2][4];
            ldsm4(a[0], aAddr + k0 * 32);
            ldsm4(a[1], aAddr + 16 * KS * 2 + k0 * 32);
            uint32_t b[4][4];
#pragma unroll
            for (int ntp = 0; ntp < 4; ntp++)
                ldsm4(b[ntp], bAddr + ntp * 16 * KS * 2 + k0 * 32);
#pragma unroll
            for (int mt = 0; mt < 2; mt++)
#pragma unroll
                for (int ntp = 0; ntp < 4; ntp++) {
                    float* c0 = c[mt][ntp * 2];
                    float* c1 = c[mt][ntp * 2 + 1];
                    asm volatile(
                        "mma.sync.aligned.m16n8k16.row.col.f32.f16.f16.f32 "
                        "{%0,%1,%2,%3}, {%4,%5,%6,%7}, {%8,%9}, {%0,%1,%2,%3};"
                        : "+f"(c0[0]), "+f"(c0[1]), "+f"(c0[2]), "+f"(c0[3])
                        : "r"(a[mt][0]), "r"(a[mt][1]), "r"(a[mt][2]), "r"(a[mt][3]),
                          "r"(b[ntp][0]), "r"(b[ntp][1]));
                    asm volatile(
                        "mma.sync.aligned.m16n8k16.row.col.f32.f16.f16.f32 "
                        "{%0,%1,%2,%3}, {%4,%5,%6,%7}, {%8,%9}, {%0,%1,%2,%3};"
                        : "+f"(c1[0]), "+f"(c1[1]), "+f"(c1[2]), "+f"(c1[3])
                        : "r"(a[mt][0]), "r"(a[mt][1]), "r"(a[mt][2]), "r"(a[mt][3]),
                          "r"(b[ntp][2]), "r"(b[ntp][3]));
                }
        }

#pragma unroll
        for (int mt = 0; mt < 2; mt++) {
            int row0 = rowBase + wm * 32 + mt * 16 + g;
            int row1 = row0 + 8;
#pragma unroll
            for (int nt = 0; nt < 8; nt++) {
                int colLoc = wn * 64 + nt * 8 + tc * 2;
                float* cc = c[mt][nt];
                if (jt < 3) {
                    size_t o0 = (size_t)row0 * 384 + jt * 128 + colLoc;
                    size_t o1 = (size_t)row1 * 384 + jt * 128 + colLoc;
                    if (row0 < NN) *(__half2*)&g_yh[o0] = __floats2half2_rn(cc[0], cc[1]);
                    if (row1 < NN) *(__half2*)&g_yh[o1] = __floats2half2_rn(cc[2], cc[3]);
                } else {
                    float b0 = linb[colLoc], b1 = linb[colLoc + 1];
                    if (row0 < NN)
                        *(float2*)&g_h[(size_t)row0 * 128 + colLoc] = make_float2(cc[0] + b0, cc[1] + b1);
                    if (row1 < NN)
                        *(float2*)&g_h[(size_t)row1 * 128 + colLoc] = make_float2(cc[2] + b0, cc[3] + b1);
                }
            }
        }
        __syncthreads();
    }
}

// ---------------- fused CSR aggregation + LayerNorm: pipelined csr prefetch ----------------
__global__ void __launch_bounds__(256)
k_aggr_ln(const float* __restrict__ gg, const float* __restrict__ gb, int mode) {
    __shared__ float shp[8][128];
    int warp = threadIdx.x >> 5, lane = threadIdx.x & 31;
    int node = blockIdx.x * 8 + warp;
    bool live = node < NN;
    float4 o = make_float4(0.f, 0.f, 0.f, 0.f);
    int c = lane * 4;

    if (live) {
        int base = g_roff[node];
        int cnt  = g_cnt[node];
        float4 hv = *(const float4*)&g_h[(size_t)node * HID + c];   // prefetch h

        float a0 = 0.f, a1 = 0.f, a2 = 0.f, a3 = 0.f;
        int v[8];
#pragma unroll
        for (int q = 0; q < 8; q++)
            v[q] = (q < cnt) ? __ldg(&g_csr[base + q]) : -1;

        int nb = (cnt + 7) >> 3;
        for (int bi = 0; bi < nb; bi++) {
            int vn[8];
            int nb0 = (bi + 1) * 8;
#pragma unroll
            for (int q = 0; q < 8; q++)
                vn[q] = (nb0 + q < cnt) ? __ldg(&g_csr[base + nb0 + q]) : -1;

            uint2 u[8];
#pragma unroll
            for (int q = 0; q < 8; q++) {
                if (v[q] >= 0) {
                    int s = v[q] >> 2, r = v[q] & 3;
                    u[q] = *(const uint2*)&g_yh[((size_t)s * NREL + r) * HID + c];
                } else {
                    u[q] = make_uint2(0u, 0u);
                }
            }
#pragma unroll
            for (int q = 0; q < 8; q++) {
                float2 f0 = __half22float2(*(__half2*)&u[q].x);
                float2 f1 = __half22float2(*(__half2*)&u[q].y);
                a0 += f0.x; a1 += f0.y; a2 += f1.x; a3 += f1.y;
            }
#pragma unroll
            for (int q = 0; q < 8; q++) v[q] = vn[q];
        }
        float di = 1.0f / fmaxf((float)cnt, 1.0f);
        hv.x += a0 * di; hv.y += a1 * di; hv.z += a2 * di; hv.w += a3 * di;

        float s = hv.x + hv.y + hv.z + hv.w;
#pragma unroll
        for (int of = 16; of; of >>= 1) s += __shfl_xor_sync(0xFFFFFFFFu, s, of);
        float mu = s * (1.0f / HID);
        float dx = hv.x - mu, dy = hv.y - mu, dz = hv.z - mu, dw = hv.w - mu;
        float s2 = dx * dx + dy * dy + dz * dz + dw * dw;
#pragma unroll
        for (int of = 16; of; of >>= 1) s2 += __shfl_xor_sync(0xFFFFFFFFu, s2, of);
        float rs = rsqrtf(s2 * (1.0f / HID) + LN_EPS);

        float4 g4 = *(const float4*)&gg[c];
        float4 b4 = *(const float4*)&gb[c];
        o = make_float4(dx * rs * g4.x + b4.x, dy * rs * g4.y + b4.y,
                        dz * rs * g4.z + b4.z, dw * rs * g4.w + b4.w);
    }

    if (mode == 0) {
        if (live) {
            __half2 h0 = __floats2half2_rn(o.x, o.y);
            __half2 h1 = __floats2half2_rn(o.z, o.w);
            *(float2*)&g_xh[(size_t)node * HID + c] =
                make_float2(__uint_as_float(*(uint32_t*)&h0), __uint_as_float(*(uint32_t*)&h1));
        }
    } else {
        shp[warp][c]     = o.x;
        shp[warp][c + 1] = o.y;
        shp[warp][c + 2] = o.z;
        shp[warp][c + 3] = o.w;
        __syncthreads();
        if (threadIdx.x < 128) {
            float s = 0.f;
#pragma unroll
            for (int w = 0; w < 8; w++) s += shp[w][threadIdx.x];
            atomicAdd(&g_pool[threadIdx.x], s);
        }
    }
}

// ---------------- regressor ----------------
__global__ void k_final(const float* __restrict__ regW, const float* __restrict__ regb,
                        float* __restrict__ out) {
    int c = threadIdx.x;
    __shared__ float red[HID];
    red[c] = g_pool[c] * (1.0f / NN) * regW[c];
    __syncthreads();
    for (int s = 64; s; s >>= 1) {
        if (c < s) red[c] += red[c + s];
        __syncthreads();
    }
    if (c == 0) out[0] = red[0] + regb[0];
}

// ---------------- launch ----------------
extern "C" void kernel_launch(void* const* d_in, const int* in_sizes, int n_in,
                              void* d_out, int out_size) {
    const int*   z     = (const int*)d_in[0];
    const float* sd    = (const float*)d_in[1];
    const float* dfp   = (const float*)d_in[2];
    const float* cond  = (const float*)d_in[3];
    const float* mult  = (const float*)d_in[4];
    const int*   ntype = (const int*)d_in[5];
    const int*   eidx  = (const int*)d_in[6];
    const int*   etyp  = (const int*)d_in[7];
    const float* zemb  = (const float*)d_in[8];
    const float* eW1   = (const float*)d_in[9];
    const float* eb1   = (const float*)d_in[10];
    const float* eW2   = (const float*)d_in[11];
    const float* eb2   = (const float*)d_in[12];
    const float* linW  = (const float*)d_in[13];
    const float* linb  = (const float*)d_in[14];
    const float* relW  = (const float*)d_in[15];
    const float* lng   = (const float*)d_in[16];
    const float* lnb   = (const float*)d_in[17];
    const float* regW  = (const float*)d_in[18];
    const float* regb  = (const float*)d_in[19];
    float* out = (float*)d_out;

    cudaFuncSetAttribute(k_encoder, cudaFuncAttributeMaxDynamicSharedMemorySize, ENC_SMEM);
    cudaFuncSetAttribute(k_mma, cudaFuncAttributeMaxDynamicSharedMemorySize, MMA_SMEM);

    const int rowBlocks = NPAD / 128;   // 782

    k_prepB<<<512, 256>>>(relW, linW);                         // 1 (weights + all zero-init)
    k_bucket_cnt<<<(EE + 255) / 256, 256>>>(ntype, eidx + EE); // 2
    k_scan1<<<(NN + 255) / 256, 256>>>();                      // 3
    k_encoder<<<dim3(rowBlocks, NTYPE), 256, ENC_SMEM>>>(      // 4  <-- ncu (encoder)
        z, sd, dfp, cond, mult, zemb, eW1, eb1, eW2, eb2);
    k_mma<<<rowBlocks, 256, MMA_SMEM>>>(0, linb);              // 5
    k_scan2<<<1, 512>>>();                                     // 6
    k_scan3<<<(NN + 255) / 256, 256>>>();                      // 7
    k_fill<<<(EE + 255) / 256, 256>>>(eidx, eidx + EE, etyp);  // 8
    k_aggr_ln<<<(NN + 7) / 8, 256>>>(lng, lnb, 0);             // 9
    k_mma<<<rowBlocks, 256, MMA_SMEM>>>(1, linb + HID);        // 10
    k_aggr_ln<<<(NN + 7) / 8, 256>>>(lng + HID, lnb + HID, 1); // 11
    k_final<<<1, 128>>>(regW, regb, out);                      // 12
}

// round 17
// speedup vs baseline: 1.2864x; 1.0185x over previous
#include <cuda_runtime.h>
#include <cuda_fp16.h>
#include <cstdint>

#define NN    100000
#define NPAD  100096
#define EE    1600000
#define HID   128
#define INDIM 20
#define NREL  3
#define NTYPE 4
#define LN_EPS 1e-5f

// ---------------- device scratch (no allocs allowed) ----------------
static __device__ float  g_h[(size_t)NN * HID];            // x@lin + b (pre-agg)
static __device__ __half g_yh[(size_t)NN * NREL * HID];    // per-relation feats fp16 (76.8MB)
static __device__ __half g_xh[(size_t)NPAD * HID];         // x (fp16); pad rows stay 0
static __device__ __half g_Bw[2 * 512 * 128];              // weights B[n][k] fp16, per layer
static __device__ int    g_cnt[NN];
static __device__ int    g_roff[NN];
static __device__ int    g_cur[NN];
static __device__ int    g_csr[EE];                        // (src<<2)|etype, grouped by dst
static __device__ int    g_bsum[512];
static __device__ int    g_tlist[(size_t)NTYPE * NN];
static __device__ int    g_tcount[NTYPE];
static __device__ float  g_pool[HID];

__device__ __forceinline__ void ldsm4(uint32_t* r, uint32_t a) {
    asm volatile("ldmatrix.sync.aligned.m8n8.x4.shared.b16 {%0,%1,%2,%3}, [%4];"
                 : "=r"(r[0]), "=r"(r[1]), "=r"(r[2]), "=r"(r[3]) : "r"(a));
}
__device__ __forceinline__ void ldsm4t(uint32_t* r, uint32_t a) {
    asm volatile("ldmatrix.sync.aligned.m8n8.x4.trans.shared.b16 {%0,%1,%2,%3}, [%4];"
                 : "=r"(r[0]), "=r"(r[1]), "=r"(r[2]), "=r"(r[3]) : "r"(a));
}
__device__ __forceinline__ void cpa16(uint32_t s, const void* g) {
    asm volatile("cp.async.cg.shared.global [%0], [%1], 16;" :: "r"(s), "l"(g));
}
#define MMA16816(cc, a0, a1, a2, a3, b0, b1)                                  \
    asm volatile(                                                             \
        "mma.sync.aligned.m16n8k16.row.col.f32.f16.f16.f32 "                  \
        "{%0,%1,%2,%3}, {%4,%5,%6,%7}, {%8,%9}, {%0,%1,%2,%3};"               \
        : "+f"(cc[0]), "+f"(cc[1]), "+f"(cc[2]), "+f"(cc[3])                  \
        : "r"(a0), "r"(a1), "r"(a2), "r"(a3), "r"(b0), "r"(b1))

// ---------------- weight prep + all zero-init (fused) ----------------
__global__ void k_prepB(const float* __restrict__ relW, const float* __restrict__ linW) {
    int i = blockIdx.x * blockDim.x + threadIdx.x;
    if (i < NN) { g_cnt[i] = 0; g_cur[i] = 0; }
    if (i < NTYPE) g_tcount[i] = 0;
    if (i < HID) g_pool[i] = 0.f;
    if (i < 512) g_bsum[i] = 0;
    if (i >= 2 * 512 * 128) return;
    int l = i >> 16;
    int rem = i & 65535;
    int n = rem >> 7, k = rem & 127;
    int jt = n >> 7, c = n & 127;
    float v = (jt < 3) ? relW[(((size_t)l * 3 + jt) * 128 + k) * 128 + c]
                       : linW[((size_t)l * 128 + k) * 128 + c];
    g_Bw[i] = __float2half_rn(v);
}

// ---------------- bucketing + degree count (fused) ----------------
__global__ void k_bucket_cnt(const int* __restrict__ ntype, const int* __restrict__ dst) {
    int i = blockIdx.x * blockDim.x + threadIdx.x;
    if (i < NN) {
        int t = ntype[i];
        int pos = atomicAdd(&g_tcount[t], 1);
        g_tlist[(size_t)t * NN + pos] = i;
    }
    if (i < EE) atomicAdd(&g_cnt[dst[i]], 1);
}

__global__ void k_scan1() {
    __shared__ int sh[256];
    int i = blockIdx.x * 256 + threadIdx.x;
    int v = (i < NN) ? g_cnt[i] : 0;
    sh[threadIdx.x] = v;
    __syncthreads();
    for (int o = 1; o < 256; o <<= 1) {
        int t = (threadIdx.x >= o) ? sh[threadIdx.x - o] : 0;
        __syncthreads();
        sh[threadIdx.x] += t;
        __syncthreads();
    }
    if (i < NN) g_roff[i] = sh[threadIdx.x] - v;
    if (threadIdx.x == 255) g_bsum[blockIdx.x] = sh[255];
}

__global__ void k_scan2() {
    __shared__ int sh[512];
    int t = threadIdx.x;
    int v = g_bsum[t];
    sh[t] = v;
    __syncthreads();
    for (int o = 1; o < 512; o <<= 1) {
        int u = (t >= o) ? sh[t - o] : 0;
        __syncthreads();
        sh[t] += u;
        __syncthreads();
    }
    g_bsum[t] = sh[t] - v;
}

__global__ void k_scan3() {
    int i = blockIdx.x * blockDim.x + threadIdx.x;
    if (i >= NN) return;
    g_roff[i] += g_bsum[i >> 8];
}

__global__ void k_fill(const int* __restrict__ src, const int* __restrict__ dst,
                       const int* __restrict__ etyp) {
    int e = blockIdx.x * blockDim.x + threadIdx.x;
    if (e >= EE) return;
    int d = dst[e];
    int pos = g_roff[d] + atomicAdd(&g_cur[d], 1);
    g_csr[pos] = (src[e] << 2) | etyp[e];
}

// ---------------- type-specific encoder: BOTH stages fp16 MMA ----------------
#define EKS 136
#define RKS 40    // raw row stride (halfs): 20r mod 32 bank-distinct for LDSM
// b1s(128f) + raws(128*RKS h) + W1s(32*EKS h) + Ah(128*EKS h) + W2s(128*EKS h)
#define ENC_SMEM (128 * 4 + (128 * RKS + 32 * EKS + 2 * 128 * EKS) * 2)

__global__ void __launch_bounds__(256, 2)
k_encoder(const int* __restrict__ z, const float* __restrict__ sd,
          const float* __restrict__ dfp, const float* __restrict__ cond,
          const float* __restrict__ mult, const float* __restrict__ zemb,
          const float* __restrict__ W1, const float* __restrict__ b1,
          const float* __restrict__ W2, const float* __restrict__ b2) {
    int t = blockIdx.y;
    int cnt = g_tcount[t];
    int start = blockIdx.x * 128;
    if (start >= cnt) return;

    extern __shared__ char smc[];
    float*  b1s  = (float*)smc;               // [128]
    __half* raws = (__half*)(b1s + 128);      // [128 n][RKS]  (raw fp16, k padded to 32)
    __half* W1s  = raws + 128 * RKS;          // [32 k][EKS]   (W1 row-major, rows 20..31 zero)
    __half* Ah   = W1s + 32 * EKS;            // [128 n][EKS]  (h1)
    __half* W2s  = Ah + 128 * EKS;            // [128 k][EKS]  (W2 row-major)
    __shared__ int nl[128];

    int tid = threadIdx.x;
    if (tid < 128) {
        int idx = start + tid;
        nl[tid] = g_tlist[(size_t)t * NN + (idx < cnt ? idx : cnt - 1)];
        b1s[tid] = b1[t * HID + tid];
    }
    // W1 [20][128] -> W1s fp16 [32][EKS] row-major; rows 20..31 zeroed
    for (int i = tid; i < 32 * 32; i += 256) {
        int k = i >> 5, c4 = (i & 31) * 4;
        float4 w = (k < INDIM) ? *(const float4*)&W1[(size_t)t * 2560 + k * 128 + c4]
                               : make_float4(0.f, 0.f, 0.f, 0.f);
        __half2 h0 = __floats2half2_rn(w.x, w.y);
        __half2 h1 = __floats2half2_rn(w.z, w.w);
        *(float2*)&W1s[k * EKS + c4] =
            make_float2(__uint_as_float(*(uint32_t*)&h0), __uint_as_float(*(uint32_t*)&h1));
    }
    // W2 [k][c] row-major fp16
    for (int i = tid; i < 4096; i += 256) {
        int k = i >> 5, c4 = (i & 31) * 4;
        float4 w = *(const float4*)&W2[(size_t)t * 16384 + k * 128 + c4];
        __half2 h0 = __floats2half2_rn(w.x, w.y);
        __half2 h1 = __floats2half2_rn(w.z, w.w);
        *(float2*)&W2s[k * EKS + c4] =
            make_float2(__uint_as_float(*(uint32_t*)&h0), __uint_as_float(*(uint32_t*)&h1));
    }
    __syncthreads();

    // build raw fp16 [128 n][32 k] (k >= 20 zero)
    for (int i = tid; i < 128 * 32; i += 256) {
        int n = i >> 5, k = i & 31;
        int node = nl[n];
        float v = 0.f;
        if (k < 16)       v = zemb[(size_t)z[node] * 16 + k];
        else if (k == 16) v = sd[node];
        else if (k == 17) v = dfp[node];
        else if (k == 18) v = cond[node];
        else if (k == 19) v = mult[node];
        raws[n * RKS + k] = __float2half_rn(v);
    }
    __syncthreads();

    int wid = tid >> 5, lane = tid & 31;
    int wm = wid >> 1, wn = wid & 1;
    int g = lane >> 2, tc = lane & 3;
    int sel = lane >> 3, lr = lane & 7;

    uint32_t rawBase = (uint32_t)__cvta_generic_to_shared(raws);
    uint32_t w1Base  = (uint32_t)__cvta_generic_to_shared(W1s);
    uint32_t ahBase  = (uint32_t)__cvta_generic_to_shared(Ah);
    uint32_t w2Base  = (uint32_t)__cvta_generic_to_shared(W2s);

    float c[2][8][4];

    // ---- stage 1: h1 = relu(raw @ W1 + b1), K=32 (2 k-steps) ----
#pragma unroll
    for (int mt = 0; mt < 2; mt++)
#pragma unroll
        for (int nt = 0; nt < 8; nt++)
#pragma unroll
            for (int q = 0; q < 4; q++) c[mt][nt][q] = 0.f;

    {
        uint32_t aAddr = rawBase + ((wm * 32 + lr + ((sel & 1) << 3)) * RKS + ((sel & 2) << 2)) * 2;
        uint32_t bAddr = w1Base + ((lr + ((sel & 1) << 3)) * EKS + wn * 64 + ((sel & 2) << 2)) * 2;
#pragma unroll
        for (int k0 = 0; k0 < 2; k0++) {
            uint32_t a[2][4];
            ldsm4(a[0], aAddr + k0 * 32);
            ldsm4(a[1], aAddr + 16 * RKS * 2 + k0 * 32);
            uint32_t b[4][4];
#pragma unroll
            for (int pr = 0; pr < 4; pr++)
                ldsm4t(b[pr], bAddr + k0 * 16 * EKS * 2 + pr * 32);
#pragma unroll
            for (int mt = 0; mt < 2; mt++)
#pragma unroll
                for (int pr = 0; pr < 4; pr++) {
                    MMA16816(c[mt][pr * 2],     a[mt][0], a[mt][1], a[mt][2], a[mt][3],
                             b[pr][0], b[pr][1]);
                    MMA16816(c[mt][pr * 2 + 1], a[mt][0], a[mt][1], a[mt][2], a[mt][3],
                             b[pr][2], b[pr][3]);
                }
        }
        // epilogue: relu(+b1) -> Ah fp16
#pragma unroll
        for (int mt = 0; mt < 2; mt++) {
            int r0 = wm * 32 + mt * 16 + g;
            int r1 = r0 + 8;
#pragma unroll
            for (int nt = 0; nt < 8; nt++) {
                int col = wn * 64 + nt * 8 + tc * 2;
                float* cc = c[mt][nt];
                float bb0 = b1s[col], bb1 = b1s[col + 1];
                __half2 h0 = __floats2half2_rn(fmaxf(cc[0] + bb0, 0.f), fmaxf(cc[1] + bb1, 0.f));
                __half2 h1 = __floats2half2_rn(fmaxf(cc[2] + bb0, 0.f), fmaxf(cc[3] + bb1, 0.f));
                *(__half2*)&Ah[r0 * EKS + col] = h0;
                *(__half2*)&Ah[r1 * EKS + col] = h1;
            }
        }
    }
    __syncthreads();

    // ---- stage 2: out = h1 @ W2 + b2, K=128 ----
#pragma unroll
    for (int mt = 0; mt < 2; mt++)
#pragma unroll
        for (int nt = 0; nt < 8; nt++)
#pragma unroll
            for (int q = 0; q < 4; q++) c[mt][nt][q] = 0.f;

    {
        uint32_t aAddr = ahBase + ((wm * 32 + lr + ((sel & 1) << 3)) * EKS + ((sel & 2) << 2)) * 2;
        uint32_t bAddr = w2Base + ((lr + ((sel & 1) << 3)) * EKS + wn * 64 + ((sel & 2) << 2)) * 2;
#pragma unroll
        for (int k0 = 0; k0 < 8; k0++) {
            uint32_t a[2][4];
            ldsm4(a[0], aAddr + k0 * 32);
            ldsm4(a[1], aAddr + 16 * EKS * 2 + k0 * 32);
            uint32_t b[4][4];
#pragma unroll
            for (int pr = 0; pr < 4; pr++)
                ldsm4t(b[pr], bAddr + k0 * 16 * EKS * 2 + pr * 32);
#pragma unroll
            for (int mt = 0; mt < 2; mt++)
#pragma unroll
                for (int pr = 0; pr < 4; pr++) {
                    MMA16816(c[mt][pr * 2],     a[mt][0], a[mt][1], a[mt][2], a[mt][3],
                             b[pr][0], b[pr][1]);
                    MMA16816(c[mt][pr * 2 + 1], a[mt][0], a[mt][1], a[mt][2], a[mt][3],
                             b[pr][2], b[pr][3]);
                }
        }
    }

#pragma unroll
    for (int mt = 0; mt < 2; mt++) {
        int lr0 = wm * 32 + mt * 16 + g;
        int lr1 = lr0 + 8;
#pragma unroll
        for (int nt = 0; nt < 8; nt++) {
            int colLoc = wn * 64 + nt * 8 + tc * 2;
            float* cc = c[mt][nt];
            float b0 = b2[t * HID + colLoc], b1v = b2[t * HID + colLoc + 1];
            if (start + lr0 < cnt)
                *(__half2*)&g_xh[(size_t)nl[lr0] * HID + colLoc] =
                    __floats2half2_rn(cc[0] + b0, cc[1] + b1v);
            if (start + lr1 < cnt)
                *(__half2*)&g_xh[(size_t)nl[lr1] * HID + colLoc] =
                    __floats2half2_rn(cc[2] + b0, cc[3] + b1v);
        }
    }
}

// ---------------- fp16 mma GEMM: LDSM fragments + cp.async double-buffered B ----------------
#define KS 136
#define AB (128 * KS)
#define MMA_SMEM ((AB + 2 * AB) * 2)

__global__ void __launch_bounds__(256, 2)
k_mma(int l, const float* __restrict__ linb) {
    extern __shared__ __half smh[];
    int tid = threadIdx.x;
    int wid = tid >> 5, lane = tid & 31;
    int rowBase = blockIdx.x * 128;
    uint32_t sbase = (uint32_t)__cvta_generic_to_shared(smh);

    for (int i = tid; i < 2048; i += 256) {
        int row = i >> 4, kc = (i & 15) * 8;
        cpa16(sbase + (row * KS + kc) * 2, &g_xh[(size_t)(rowBase + row) * 128 + kc]);
    }
    const __half* gB = g_Bw + (size_t)l * 512 * 128;
    for (int i = tid; i < 2048; i += 256) {
        int row = i >> 4, kc = (i & 15) * 8;
        cpa16(sbase + (AB + row * KS + kc) * 2, gB + (size_t)row * 128 + kc);
    }
    asm volatile("cp.async.commit_group;" ::: "memory");

    int wm = wid >> 1, wn = wid & 1;
    int sel = lane >> 3, lr = lane & 7;
    int g = lane >> 2, tc = lane & 3;

    int arow = wm * 32 + lr + ((sel & 1) << 3);
    int acol = (sel & 2) << 2;
    uint32_t aAddr = sbase + (arow * KS + acol) * 2;
    int brow = wn * 64 + lr + ((sel & 2) << 2);
    int bcol = (sel & 1) << 3;
    uint32_t bOff = (brow * KS + bcol) * 2;

    for (int jt = 0; jt < 4; jt++) {
        asm volatile("cp.async.wait_group 0;" ::: "memory");
        __syncthreads();
        if (jt < 3) {
            const __half* gBn = gB + (size_t)(jt + 1) * 128 * 128;
            int bufn = (jt + 1) & 1;
            for (int i = tid; i < 2048; i += 256) {
                int row = i >> 4, kc = (i & 15) * 8;
                cpa16(sbase + (AB + bufn * AB + row * KS + kc) * 2,
                      gBn + (size_t)row * 128 + kc);
            }
            asm volatile("cp.async.commit_group;" ::: "memory");
        }
        uint32_t bAddr = sbase + (AB + (jt & 1) * AB) * 2 + bOff;

        float c[2][8][4];
#pragma unroll
        for (int mt = 0; mt < 2; mt++)
#pragma unroll
            for (int nt = 0; nt < 8; nt++)
#pragma unroll
                for (int q = 0; q < 4; q++) c[mt][nt][q] = 0.f;

#pragma unroll
        for (int k0 = 0; k0 < 8; k0++) {
            uint32_t a[2][4];
            ldsm4(a[0], aAddr + k0 * 32);
            ldsm4(a[1], aAddr + 16 * KS * 2 + k0 * 32);
            uint32_t b[4][4];
#pragma unroll
            for (int ntp = 0; ntp < 4; ntp++)
                ldsm4(b[ntp], bAddr + ntp * 16 * KS * 2 + k0 * 32);
#pragma unroll
            for (int mt = 0; mt < 2; mt++)
#pragma unroll
                for (int ntp = 0; ntp < 4; ntp++) {
                    MMA16816(c[mt][ntp * 2],     a[mt][0], a[mt][1], a[mt][2], a[mt][3],
                             b[ntp][0], b[ntp][1]);
                    MMA16816(c[mt][ntp * 2 + 1], a[mt][0], a[mt][1], a[mt][2], a[mt][3],
                             b[ntp][2], b[ntp][3]);
                }
        }

#pragma unroll
        for (int mt = 0; mt < 2; mt++) {
            int row0 = rowBase + wm * 32 + mt * 16 + g;
            int row1 = row0 + 8;
#pragma unroll
            for (int nt = 0; nt < 8; nt++) {
                int colLoc = wn * 64 + nt * 8 + tc * 2;
                float* cc = c[mt][nt];
                if (jt < 3) {
                    size_t o0 = (size_t)row0 * 384 + jt * 128 + colLoc;
                    size_t o1 = (size_t)row1 * 384 + jt * 128 + colLoc;
                    if (row0 < NN) *(__half2*)&g_yh[o0] = __floats2half2_rn(cc[0], cc[1]);
                    if (row1 < NN) *(__half2*)&g_yh[o1] = __floats2half2_rn(cc[2], cc[3]);
                } else {
                    float b0 = linb[colLoc], b1 = linb[colLoc + 1];
                    if (row0 < NN)
                        *(float2*)&g_h[(size_t)row0 * 128 + colLoc] = make_float2(cc[0] + b0, cc[1] + b1);
                    if (row1 < NN)
                        *(float2*)&g_h[(size_t)row1 * 128 + colLoc] = make_float2(cc[2] + b0, cc[3] + b1);
                }
            }
        }
        __syncthreads();
    }
}

// ---------------- fused CSR aggregation + LayerNorm: pipelined csr prefetch ----------------
__global__ void __launch_bounds__(256)
k_aggr_ln(const float* __restrict__ gg, const float* __restrict__ gb, int mode) {
    __shared__ float shp[8][128];
    int warp = threadIdx.x >> 5, lane = threadIdx.x & 31;
    int node = blockIdx.x * 8 + warp;
    bool live = node < NN;
    float4 o = make_float4(0.f, 0.f, 0.f, 0.f);
    int c = lane * 4;

    if (live) {
        int base = g_roff[node];
        int cnt  = g_cnt[node];
        float4 hv = *(const float4*)&g_h[(size_t)node * HID + c];   // prefetch h

        float a0 = 0.f, a1 = 0.f, a2 = 0.f, a3 = 0.f;
        int v[8];
#pragma unroll
        for (int q = 0; q < 8; q++)
            v[q] = (q < cnt) ? __ldg(&g_csr[base + q]) : -1;

        int nb = (cnt + 7) >> 3;
        for (int bi = 0; bi < nb; bi++) {
            int vn[8];
            int nb0 = (bi + 1) * 8;
#pragma unroll
            for (int q = 0; q < 8; q++)
                vn[q] = (nb0 + q < cnt) ? __ldg(&g_csr[base + nb0 + q]) : -1;

            uint2 u[8];
#pragma unroll
            for (int q = 0; q < 8; q++) {
                if (v[q] >= 0) {
                    int s = v[q] >> 2, r = v[q] & 3;
                    u[q] = *(const uint2*)&g_yh[((size_t)s * NREL + r) * HID + c];
                } else {
                    u[q] = make_uint2(0u, 0u);
                }
            }
#pragma unroll
            for (int q = 0; q < 8; q++) {
                float2 f0 = __half22float2(*(__half2*)&u[q].x);
                float2 f1 = __half22float2(*(__half2*)&u[q].y);
                a0 += f0.x; a1 += f0.y; a2 += f1.x; a3 += f1.y;
            }
#pragma unroll
            for (int q = 0; q < 8; q++) v[q] = vn[q];
        }
        float di = 1.0f / fmaxf((float)cnt, 1.0f);
        hv.x += a0 * di; hv.y += a1 * di; hv.z += a2 * di; hv.w += a3 * di;

        float s = hv.x + hv.y + hv.z + hv.w;
#pragma unroll
        for (int of = 16; of; of >>= 1) s += __shfl_xor_sync(0xFFFFFFFFu, s, of);
        float mu = s * (1.0f / HID);
        float dx = hv.x - mu, dy = hv.y - mu, dz = hv.z - mu, dw = hv.w - mu;
        float s2 = dx * dx + dy * dy + dz * dz + dw * dw;
#pragma unroll
        for (int of = 16; of; of >>= 1) s2 += __shfl_xor_sync(0xFFFFFFFFu, s2, of);
        float rs = rsqrtf(s2 * (1.0f / HID) + LN_EPS);

        float4 g4 = *(const float4*)&gg[c];
        float4 b4 = *(const float4*)&gb[c];
        o = make_float4(dx * rs * g4.x + b4.x, dy * rs * g4.y + b4.y,
                        dz * rs * g4.z + b4.z, dw * rs * g4.w + b4.w);
    }

    if (mode == 0) {
        if (live) {
            __half2 h0 = __floats2half2_rn(o.x, o.y);
            __half2 h1 = __floats2half2_rn(o.z, o.w);
            *(float2*)&g_xh[(size_t)node * HID + c] =
                make_float2(__uint_as_float(*(uint32_t*)&h0), __uint_as_float(*(uint32_t*)&h1));
        }
    } else {
        shp[warp][c]     = o.x;
        shp[warp][c + 1] = o.y;
        shp[warp][c + 2] = o.z;
        shp[warp][c + 3] = o.w;
        __syncthreads();
        if (threadIdx.x < 128) {
            float s = 0.f;
#pragma unroll
            for (int w = 0; w < 8; w++) s += shp[w][threadIdx.x];
            atomicAdd(&g_pool[threadIdx.x], s);
        }
    }
}

// ---------------- regressor ----------------
__global__ void k_final(const float* __restrict__ regW, const float* __restrict__ regb,
                        float* __restrict__ out) {
    int c = threadIdx.x;
    __shared__ float red[HID];
    red[c] = g_pool[c] * (1.0f / NN) * regW[c];
    __syncthreads();
    for (int s = 64; s; s >>= 1) {
        if (c < s) red[c] += red[c + s];
        __syncthreads();
    }
    if (c == 0) out[0] = red[0] + regb[0];
}

// ---------------- launch ----------------
extern "C" void kernel_launch(void* const* d_in, const int* in_sizes, int n_in,
                              void* d_out, int out_size) {
    const int*   z     = (const int*)d_in[0];
    const float* sd    = (const float*)d_in[1];
    const float* dfp   = (const float*)d_in[2];
    const float* cond  = (const float*)d_in[3];
    const float* mult  = (const float*)d_in[4];
    const int*   ntype = (const int*)d_in[5];
    const int*   eidx  = (const int*)d_in[6];
    const int*   etyp  = (const int*)d_in[7];
    const float* zemb  = (const float*)d_in[8];
    const float* eW1   = (const float*)d_in[9];
    const float* eb1   = (const float*)d_in[10];
    const float* eW2   = (const float*)d_in[11];
    const float* eb2   = (const float*)d_in[12];
    const float* linW  = (const float*)d_in[13];
    const float* linb  = (const float*)d_in[14];
    const float* relW  = (const float*)d_in[15];
    const float* lng   = (const float*)d_in[16];
    const float* lnb   = (const float*)d_in[17];
    const float* regW  = (const float*)d_in[18];
    const float* regb  = (const float*)d_in[19];
    float* out = (float*)d_out;

    cudaFuncSetAttribute(k_encoder, cudaFuncAttributeMaxDynamicSharedMemorySize, ENC_SMEM);
    cudaFuncSetAttribute(k_mma, cudaFuncAttributeMaxDynamicSharedMemorySize, MMA_SMEM);

    const int rowBlocks = NPAD / 128;   // 782

    k_prepB<<<512, 256>>>(relW, linW);                         // 1 (weights + all zero-init)
    k_bucket_cnt<<<(EE + 255) / 256, 256>>>(ntype, eidx + EE); // 2
    k_scan1<<<(NN + 255) / 256, 256>>>();                      // 3
    k_encoder<<<dim3(rowBlocks, NTYPE), 256, ENC_SMEM>>>(      // 4  <-- ncu (encoder)
        z, sd, dfp, cond, mult, zemb, eW1, eb1, eW2, eb2);
    k_mma<<<rowBlocks, 256, MMA_SMEM>>>(0, linb);              // 5
    k_scan2<<<1, 512>>>();                                     // 6
    k_scan3<<<(NN + 255) / 256, 256>>>();                      // 7
    k_fill<<<(EE + 255) / 256, 256>>>(eidx, eidx + EE, etyp);  // 8
    k_aggr_ln<<<(NN + 7) / 8, 256>>>(lng, lnb, 0);             // 9
    k_mma<<<rowBlocks, 256, MMA_SMEM>>>(1, linb + HID);        // 10
    k_aggr_ln<<<(NN + 7) / 8, 256>>>(lng + HID, lnb + HID, 1); // 11
    k_final<<<1, 128>>>(regW, regb, out);                      // 12
}